// round 14
// baseline (speedup 1.0000x reference)
#include <cuda_runtime.h>
#include <math.h>

#define NB 4096

// Per-box SAT data in smem: 2 float4 per box
//  v0 = (cx, cy, a0x, a0y)   center + edge vector 0
//  v1 = (a1x, a1y, L0, L1)   edge vector 1, L = |a|^2
// plus per-box enclosing-circle radius R = 0.5*sqrt(w^2+h^2)

__device__ __forceinline__ float giou_eval(float La, float Lb, float S,
                                           float t_in, float d) {
    float th    = fmaf(0.5f, S, fabsf(d));
    float inter = fminf(fminf(La, Lb), t_in);
    float hull  = fmaxf(fmaxf(La, Lb), th);
    float uni   = S - inter;               // > 0 always
    float tmp   = fmaf(2.0f, inter, -S);   // inter - uni
    float N     = fmaf(uni, uni, tmp * hull);
    return __fdividef(N, uni * hull);
}

__global__ __launch_bounds__(256) void pair_kernel(
    const float* __restrict__ boxes, float* __restrict__ out)
{
    __shared__ float4 sI[64 * 2];
    __shared__ float4 sJ[64 * 2];
    __shared__ float  sRI[64];
    __shared__ float  sRJ[64];
    __shared__ float  smT[64][68];              // [jloc][iloc], 16B-aligned rows
    __shared__ unsigned short s_wwl[8][512];    // per-warp worklists

    // linear bid -> (rt, ct), rt <= ct (64x64 tiles, upper triangle incl diag)
    const int b = blockIdx.x;
    int ct = (int)(0.5f * (sqrtf(8.0f * (float)b + 1.0f) - 1.0f));
    if ((ct + 1) * (ct + 2) / 2 <= b) ct++;
    if (ct * (ct + 1) / 2 > b) ct--;
    const int rt = b - ct * (ct + 1) / 2;

    const int ti = rt * 64;
    const int tj = ct * 64;
    const int t  = threadIdx.x;

    // Build SAT data + radius for this tile's boxes (I rows, J cols)
    if (t < 128) {
        const int isJ = (t >= 64);
        const int loc = t & 63;
        const int gb  = isJ ? (tj + loc) : (ti + loc);
        const float* bp = boxes + gb * 5;
        float cx = bp[0], cy = bp[1], w = bp[2], h = bp[3], ang = bp[4];
        float s, c;
        __sincosf(ang, &s, &c);
        float4 v0 = make_float4(cx, cy, w * c, -w * s);
        float4 v1 = make_float4(h * s, h * c, w * w, h * h);
        float R = 0.5f * sqrtf(fmaf(w, w, h * h));
        if (isJ) { sJ[loc * 2] = v0; sJ[loc * 2 + 1] = v1; sRJ[loc] = R; }
        else     { sI[loc * 2] = v0; sI[loc * 2 + 1] = v1; sRI[loc] = R; }
    }
    // zero-fill smT (64*68 = 4352 floats = 1088 float4)
    {
        float4* z4 = (float4*)&smT[0][0];
        float4 zz = make_float4(0.f, 0.f, 0.f, 0.f);
        for (int k = t; k < 1088; k += 256) z4[k] = zz;
    }
    __syncthreads();

    const int tx = t & 31;
    const int ty = t >> 5;
    const bool diagTile = (rt == ct);
    const unsigned lmask_lt = (1u << tx) - 1u;
    unsigned short* const mywl = &s_wwl[ty][0];

    // two adjacent j columns per lane: j0 = 2*tx, j1 = 2*tx+1
    const int j0 = 2 * tx;
    const int j1 = j0 + 1;
    const float4 Jv0 = sJ[j0 * 2];
    const float4 Jv1 = sJ[j1 * 2];
    const float Rj0 = sRJ[j0];
    const float Rj1 = sRJ[j1];

    // ---- Phase 1: circle prefilter; coalesced zero stores; warp compaction ----
    int wcnt = 0;   // uniform across the warp
#pragma unroll
    for (int ii = 0; ii < 8; ii++) {
        const int iloc = ty * 8 + ii;
        const float4 Iv = sI[iloc * 2];
        const float Ri = sRI[iloc];

        float dcx0 = Jv0.x - Iv.x, dcy0 = Jv0.y - Iv.y;
        float dcx1 = Jv1.x - Iv.x, dcy1 = Jv1.y - Iv.y;
        float rs0 = Ri + Rj0, rs1 = Ri + Rj1;
        float n20 = fmaf(dcx0, dcx0, dcy0 * dcy0);
        float n21 = fmaf(dcx1, dcx1, dcy1 * dcy1);
        bool push0 = fmaf(rs0, rs0, -n20) > 0.0f;
        bool push1 = fmaf(rs1, rs1, -n21) > 0.0f;
        if (diagTile) {
            if (iloc == j0) push0 = false;
            if (iloc == j1) push1 = false;
        }

        // zero both normal-orientation outputs with one STG.64
        ((float2*)(out + (size_t)(ti + iloc) * NB + tj))[tx] = make_float2(0.f, 0.f);

        unsigned m0 = __ballot_sync(0xffffffffu, push0);
        if (push0) mywl[wcnt + __popc(m0 & lmask_lt)] =
            (unsigned short)(iloc | (j0 << 8));
        wcnt += __popc(m0);
        unsigned m1 = __ballot_sync(0xffffffffu, push1);
        if (push1) mywl[wcnt + __popc(m1 & lmask_lt)] =
            (unsigned short)(iloc | (j1 << 8));
        wcnt += __popc(m1);
    }
    __syncwarp();

    // ---- Phase 2: dense SAT + giou on this warp's worklist ----
    for (int k = tx; k < wcnt; k += 32) {
        const int e = mywl[k];
        const int iloc = e & 255;
        const int jloc = e >> 8;
        const float4 Ia  = sI[iloc * 2 + 0];
        const float4 Ib  = sI[iloc * 2 + 1];
        const float4 Jav = sJ[jloc * 2 + 0];
        const float4 Jbv = sJ[jloc * 2 + 1];

        const float a0ix = Ia.z, a0iy = Ia.w, a1ix = Ib.x, a1iy = Ib.y;
        const float a0jx = Jav.z, a0jy = Jav.w, a1jx = Jbv.x, a1jy = Jbv.y;

        float dcx = Jav.x - Ia.x;
        float dcy = Jav.y - Ia.y;

        float M00 = fmaf(a0ix, a0jx, a0iy * a0jy);
        float M01 = fmaf(a0ix, a1jx, a0iy * a1jy);
        float M10 = fmaf(a1ix, a0jx, a1iy * a0jy);
        float M11 = fmaf(a1ix, a1jx, a1iy * a1jy);

        float dA0 = fmaf(dcx, a0ix, dcy * a0iy);
        float dA1 = fmaf(dcx, a1ix, dcy * a1iy);
        float dB0 = fmaf(dcx, a0jx, dcy * a0jy);
        float dB1 = fmaf(dcx, a1jx, dcy * a1jy);

        float LbA0 = fabsf(M00) + fabsf(M01);
        float LbA1 = fabsf(M10) + fabsf(M11);
        float LbB0 = fabsf(M00) + fabsf(M10);
        float LbB1 = fabsf(M01) + fabsf(M11);

        float S0 = Ib.z  + LbA0;
        float S1 = Ib.w  + LbA1;
        float S2 = Jbv.z + LbB0;
        float S3 = Jbv.w + LbB1;

        float t0 = fmaf(0.5f, S0, -fabsf(dA0));
        float t1 = fmaf(0.5f, S1, -fabsf(dA1));
        float t2 = fmaf(0.5f, S2, -fabsf(dB0));
        float t3 = fmaf(0.5f, S3, -fabsf(dB1));
        float m = fminf(fminf(t0, t1), fminf(t2, t3));

        float g0 = giou_eval(Ib.z,  LbA0, S0, t0, dA0);
        float g1 = giou_eval(Ib.w,  LbA1, S1, t1, dA1);
        float g2 = giou_eval(Jbv.z, LbB0, S2, t2, dB0);
        float g3 = giou_eval(Jbv.w, LbB1, S3, t3, dB1);

        float gmin = fminf(fminf(g0, g1), fminf(g2, g3));
        float res = (m > 0.0f) ? fmaxf(gmin, 0.0f) : 0.0f;

        out[(size_t)(ti + iloc) * NB + tj + jloc] = res;
        smT[jloc][iloc] = res;
    }

    __syncthreads();

    // ---- Mirror writeback: out[tj+r][ti+c], LDS.128 + STG.128 ----
    {
        const int r  = t >> 2;          // 0..63
        const int c0 = (t & 3) * 16;    // 0,16,32,48
        const float4* src = (const float4*)&smT[r][c0];
        float4* dst = (float4*)(out + (size_t)(tj + r) * NB + ti + c0);
#pragma unroll
        for (int k = 0; k < 4; k++) dst[k] = src[k];
    }
}

extern "C" void kernel_launch(void* const* d_in, const int* in_sizes, int n_in,
                              void* d_out, int out_size) {
    const float* boxes = (const float*)d_in[0];
    float* out = (float*)d_out;
    (void)in_sizes; (void)n_in; (void)out_size;

    // tiles with rt <= ct, 64 col-tiles: 64*65/2 = 2080
    pair_kernel<<<2080, 256>>>(boxes, out);
}

// round 15
// speedup vs baseline: 1.1082x; 1.1082x over previous
#include <cuda_runtime.h>
#include <math.h>

#define NB 4096

// Per-box SAT data in smem: 2 float4 per box
//  v0 = (cx, cy, a0x, a0y)   center + edge vector 0
//  v1 = (a1x, a1y, L0, L1)   edge vector 1, L = |a|^2
// plus per-box enclosing-circle radius R = 0.5*sqrt(w^2+h^2)

__device__ __forceinline__ float giou_eval(float La, float Lb, float S,
                                           float t_in, float d) {
    float th    = fmaf(0.5f, S, fabsf(d));
    float inter = fminf(fminf(La, Lb), t_in);
    float hull  = fmaxf(fmaxf(La, Lb), th);
    float uni   = S - inter;               // > 0 always
    float tmp   = fmaf(2.0f, inter, -S);   // inter - uni
    float N     = fmaf(uni, uni, tmp * hull);
    return __fdividef(N, uni * hull);
}

__global__ __launch_bounds__(256) void pair_kernel(
    const float* __restrict__ boxes, float* __restrict__ out)
{
    __shared__ float4 sI[32 * 2];
    __shared__ float4 sJ[64 * 2];
    __shared__ float  sRI[32];
    __shared__ float  sRJ[64];
    __shared__ float  smT[64][36];              // [jloc][iloc], 16B-aligned rows
    __shared__ unsigned short s_wwl[8][256];    // per-warp worklists

    // linear bid -> (ct, rt) over tiles with rt <= 2*ct+1
    const int b = blockIdx.x;
    int ct = (int)(0.5f * (sqrtf(4.0f * (float)b + 1.0f) - 1.0f));
    if ((ct + 1) * (ct + 2) <= b) ct++;
    if (ct * (ct + 1) > b) ct--;
    const int rt = b - ct * (ct + 1);

    const int ti = rt * 32;
    const int tj = ct * 64;
    const int t  = threadIdx.x;

    // Build SAT data + radius for this tile's 96 boxes
    if (t < 96) {
        const int isJ = (t >= 32);
        const int loc = isJ ? (t - 32) : t;
        const int gb  = isJ ? (tj + loc) : (ti + loc);
        const float* bp = boxes + gb * 5;
        float cx = bp[0], cy = bp[1], w = bp[2], h = bp[3], ang = bp[4];
        float s, c;
        __sincosf(ang, &s, &c);
        float4 v0 = make_float4(cx, cy, w * c, -w * s);
        float4 v1 = make_float4(h * s, h * c, w * w, h * h);
        float R = 0.5f * sqrtf(fmaf(w, w, h * h));
        if (isJ) { sJ[loc * 2] = v0; sJ[loc * 2 + 1] = v1; sRJ[loc] = R; }
        else     { sI[loc * 2] = v0; sI[loc * 2 + 1] = v1; sRI[loc] = R; }
    }
    // zero-fill smT once, vectorized: 64*36 = 2304 floats = 576 float4
    {
        float4* z4 = (float4*)&smT[0][0];
        float4 zz = make_float4(0.f, 0.f, 0.f, 0.f);
        for (int k = t; k < 576; k += 256) z4[k] = zz;
    }
    __syncthreads();

    const int tx = t & 31;
    const int ty = t >> 5;
    const bool diagTile = (rt >= 2 * ct);
    const unsigned lmask_lt = (1u << tx) - 1u;
    unsigned short* const mywl = &s_wwl[ty][0];

    // Zero this warp's 4 output rows (ti+4ty .. ti+4ty+3), cols tj..tj+63:
    // 4 rows * 16 float4 = 64 float4 per warp -> 2 STG.128 per lane.
    {
        float4 zz = make_float4(0.f, 0.f, 0.f, 0.f);
#pragma unroll
        for (int k = 0; k < 2; k++) {
            int idx = tx + k * 32;            // 0..63
            int row = ty * 4 + (idx >> 4);    // 4 rows
            int seg = idx & 15;               // 16 float4 per row
            ((float4*)(out + (size_t)(ti + row) * NB + tj))[seg] = zz;
        }
    }

    // j-side circle data in registers
    float Jcx[2], Jcy[2], Rj[2];
#pragma unroll
    for (int jj = 0; jj < 2; jj++) {
        int jl = tx + jj * 32;
        float4 v = sJ[jl * 2];
        Jcx[jj] = v.x; Jcy[jj] = v.y;
        Rj[jj] = sRJ[jl];
    }

    // ---- Phase 1: circle prefilter; warp-local compaction (no stores) ----
    int wcnt = 0;   // uniform across the warp
#pragma unroll
    for (int ii = 0; ii < 4; ii++) {
        const int iloc = ty * 4 + ii;
        const float4 Iv = sI[iloc * 2];
        const float Ri = sRI[iloc];

#pragma unroll
        for (int jj = 0; jj < 2; jj++) {
            const int jloc = tx + jj * 32;
            float dcx = Jcx[jj] - Iv.x;
            float dcy = Jcy[jj] - Iv.y;
            float rs  = Ri + Rj[jj];
            float n2  = fmaf(dcx, dcx, dcy * dcy);
            bool push = fmaf(rs, rs, -n2) > 0.0f;
            if (diagTile && (ti + iloc == tj + jloc)) push = false;

            unsigned msk = __ballot_sync(0xffffffffu, push);
            if (push) {
                int pos = wcnt + __popc(msk & lmask_lt);
                mywl[pos] = (unsigned short)(iloc | (jloc << 8));
            }
            wcnt += __popc(msk);
        }
    }
    __syncwarp();

    // ---- Phase 2: dense SAT + giou on this warp's worklist ----
    // out scatter targets this warp's own rows (zeroed above, after syncwarp);
    // smT scatter targets arbitrary rows but smT was zeroed before __syncthreads.
    for (int k = tx; k < wcnt; k += 32) {
        const int e = mywl[k];
        const int iloc = e & 255;
        const int jloc = e >> 8;
        const float4 Ia  = sI[iloc * 2 + 0];
        const float4 Ib  = sI[iloc * 2 + 1];
        const float4 Jav = sJ[jloc * 2 + 0];
        const float4 Jbv = sJ[jloc * 2 + 1];

        const float a0ix = Ia.z, a0iy = Ia.w, a1ix = Ib.x, a1iy = Ib.y;
        const float a0jx = Jav.z, a0jy = Jav.w, a1jx = Jbv.x, a1jy = Jbv.y;

        float dcx = Jav.x - Ia.x;
        float dcy = Jav.y - Ia.y;

        float M00 = fmaf(a0ix, a0jx, a0iy * a0jy);
        float M01 = fmaf(a0ix, a1jx, a0iy * a1jy);
        float M10 = fmaf(a1ix, a0jx, a1iy * a0jy);
        float M11 = fmaf(a1ix, a1jx, a1iy * a1jy);

        float dA0 = fmaf(dcx, a0ix, dcy * a0iy);
        float dA1 = fmaf(dcx, a1ix, dcy * a1iy);
        float dB0 = fmaf(dcx, a0jx, dcy * a0jy);
        float dB1 = fmaf(dcx, a1jx, dcy * a1jy);

        float LbA0 = fabsf(M00) + fabsf(M01);
        float LbA1 = fabsf(M10) + fabsf(M11);
        float LbB0 = fabsf(M00) + fabsf(M10);
        float LbB1 = fabsf(M01) + fabsf(M11);

        float S0 = Ib.z  + LbA0;
        float S1 = Ib.w  + LbA1;
        float S2 = Jbv.z + LbB0;
        float S3 = Jbv.w + LbB1;

        float t0 = fmaf(0.5f, S0, -fabsf(dA0));
        float t1 = fmaf(0.5f, S1, -fabsf(dA1));
        float t2 = fmaf(0.5f, S2, -fabsf(dB0));
        float t3 = fmaf(0.5f, S3, -fabsf(dB1));
        float m = fminf(fminf(t0, t1), fminf(t2, t3));

        float g0 = giou_eval(Ib.z,  LbA0, S0, t0, dA0);
        float g1 = giou_eval(Ib.w,  LbA1, S1, t1, dA1);
        float g2 = giou_eval(Jbv.z, LbB0, S2, t2, dB0);
        float g3 = giou_eval(Jbv.w, LbB1, S3, t3, dB1);

        float gmin = fminf(fminf(g0, g1), fminf(g2, g3));
        float res = (m > 0.0f) ? fmaxf(gmin, 0.0f) : 0.0f;

        out[(size_t)(ti + iloc) * NB + tj + jloc] = res;
        smT[jloc][iloc] = res;
    }

    __syncthreads();

    // ---- Mirror writeback: out[tj+r][ti+c], 2x (LDS.128 + STG.128) ----
    {
        const int r  = t >> 2;          // 0..63
        const int c0 = (t & 3) * 8;     // 0,8,16,24
        const float4* src = (const float4*)&smT[r][c0];
        float4* dst = (float4*)(out + (size_t)(tj + r) * NB + ti + c0);
        dst[0] = src[0];
        dst[1] = src[1];
    }
}

extern "C" void kernel_launch(void* const* d_in, const int* in_sizes, int n_in,
                              void* d_out, int out_size) {
    const float* boxes = (const float*)d_in[0];
    float* out = (float*)d_out;
    (void)in_sizes; (void)n_in; (void)out_size;

    pair_kernel<<<4160, 256>>>(boxes, out);
}

// round 16
// speedup vs baseline: 1.2301x; 1.1100x over previous
#include <cuda_runtime.h>
#include <math.h>

#define NB 4096

// Per-box SAT data in smem: 2 float4 per box
//  v0 = (cx, cy, a0x, a0y)   center + edge vector 0
//  v1 = (a1x, a1y, L0, L1)   edge vector 1, L = |a|^2
// plus per-box enclosing-circle radius R = 0.5*sqrt(w^2+h^2)

__device__ __forceinline__ float giou_eval(float La, float Lb, float S,
                                           float t_in, float d) {
    float th    = fmaf(0.5f, S, fabsf(d));
    float inter = fminf(fminf(La, Lb), t_in);
    float hull  = fmaxf(fmaxf(La, Lb), th);
    float uni   = S - inter;               // > 0 always
    float tmp   = fmaf(2.0f, inter, -S);   // inter - uni
    float N     = fmaf(uni, uni, tmp * hull);
    return __fdividef(N, uni * hull);
}

__global__ __launch_bounds__(256) void pair_kernel(
    const float* __restrict__ boxes, float* __restrict__ out)
{
    __shared__ float4 sI[32 * 2];
    __shared__ float4 sJ[64 * 2];
    __shared__ float  sRI[32];
    __shared__ float  sRJ[64];
    __shared__ unsigned char s_wwl[8][256];   // per-warp worklists (1B entries)

    // linear bid -> (ct, rt) over tiles with rt <= 2*ct+1
    const int b = blockIdx.x;
    int ct = (int)(0.5f * (sqrtf(4.0f * (float)b + 1.0f) - 1.0f));
    if ((ct + 1) * (ct + 2) <= b) ct++;
    if (ct * (ct + 1) > b) ct--;
    const int rt = b - ct * (ct + 1);

    const int ti = rt * 32;
    const int tj = ct * 64;
    const int t  = threadIdx.x;

    // Build SAT data + radius for this tile's 96 boxes
    if (t < 96) {
        const int isJ = (t >= 32);
        const int loc = isJ ? (t - 32) : t;
        const int gb  = isJ ? (tj + loc) : (ti + loc);
        const float* bp = boxes + gb * 5;
        float cx = bp[0], cy = bp[1], w = bp[2], h = bp[3], ang = bp[4];
        float s, c;
        __sincosf(ang, &s, &c);
        float4 v0 = make_float4(cx, cy, w * c, -w * s);
        float4 v1 = make_float4(h * s, h * c, w * w, h * h);
        float R = 0.5f * sqrtf(fmaf(w, w, h * h));
        if (isJ) { sJ[loc * 2] = v0; sJ[loc * 2 + 1] = v1; sRJ[loc] = R; }
        else     { sI[loc * 2] = v0; sI[loc * 2 + 1] = v1; sRI[loc] = R; }
    }

    // Zero mirror region: rows [tj, tj+64), cols [ti, ti+32): 512 float4.
    {
        float4 zz = make_float4(0.f, 0.f, 0.f, 0.f);
#pragma unroll
        for (int k = 0; k < 2; k++) {
            int idx = t + k * 256;            // 0..511
            int row = idx >> 3;               // 64 rows
            int seg = idx & 7;                // 8 float4 per row
            ((float4*)(out + (size_t)(tj + row) * NB + ti))[seg] = zz;
        }
    }
    __syncthreads();

    const int tx = t & 31;
    const int ty = t >> 5;
    const bool diagTile = (rt >= 2 * ct);
    unsigned char* const mywl = &s_wwl[ty][0];

    // Zero this warp's 4 normal rows (ti+4ty..+3), cols tj..tj+63.
    {
        float4 zz = make_float4(0.f, 0.f, 0.f, 0.f);
#pragma unroll
        for (int k = 0; k < 2; k++) {
            int idx = tx + k * 32;            // 0..63
            int row = ty * 4 + (idx >> 4);
            int seg = idx & 15;
            ((float4*)(out + (size_t)(ti + row) * NB + tj))[seg] = zz;
        }
    }

    // j-side circle data in registers
    float Jcx[2], Jcy[2], Rj[2];
#pragma unroll
    for (int jj = 0; jj < 2; jj++) {
        int jl = tx + jj * 32;
        float4 v = sJ[jl * 2];
        Jcx[jj] = v.x; Jcy[jj] = v.y;
        Rj[jj] = sRJ[jl];
    }

    // ---- Phase 1: circle prefilter -> per-thread 8-bit mask ----
    unsigned mask = 0;
#pragma unroll
    for (int ii = 0; ii < 4; ii++) {
        const int iloc = ty * 4 + ii;
        const float4 Iv = sI[iloc * 2];
        const float Ri = sRI[iloc];
#pragma unroll
        for (int jj = 0; jj < 2; jj++) {
            const int jloc = tx + jj * 32;
            float dcx = Jcx[jj] - Iv.x;
            float dcy = Jcy[jj] - Iv.y;
            float rs  = Ri + Rj[jj];
            float n2  = fmaf(dcx, dcx, dcy * dcy);
            bool push = fmaf(rs, rs, -n2) > 0.0f;
            if (diagTile && (ti + iloc == tj + jloc)) push = false;
            if (push) mask |= 1u << (ii * 2 + jj);
        }
    }

    // ---- Warp-wide compaction via one inclusive scan ----
    int cnt = __popc(mask);
    int incl = cnt;
#pragma unroll
    for (int d = 1; d < 32; d <<= 1) {
        int n = __shfl_up_sync(0xffffffffu, incl, d);
        if (tx >= d) incl += n;
    }
    int base = incl - cnt;
    const int wcnt = __shfl_sync(0xffffffffu, incl, 31);
    unsigned mm = mask;
    while (mm) {
        int k = __ffs(mm) - 1;
        mm &= mm - 1;
        mywl[base++] = (unsigned char)((k << 5) | tx);
    }
    // All zero-stores CTA-wide must land before any scattered overwrite
    // (straddle tiles: mirror region overlaps another warp's scatter targets).
    __syncthreads();

    // ---- Phase 2: dense SAT + giou on this warp's worklist ----
    for (int k = tx; k < wcnt; k += 32) {
        const int e = mywl[k];
        const int lane = e & 31;
        const int kk   = e >> 5;
        const int iloc = ty * 4 + (kk >> 1);
        const int jloc = lane + (kk & 1) * 32;

        const float4 Ia  = sI[iloc * 2 + 0];
        const float4 Ib  = sI[iloc * 2 + 1];
        const float4 Jav = sJ[jloc * 2 + 0];
        const float4 Jbv = sJ[jloc * 2 + 1];

        const float a0ix = Ia.z, a0iy = Ia.w, a1ix = Ib.x, a1iy = Ib.y;
        const float a0jx = Jav.z, a0jy = Jav.w, a1jx = Jbv.x, a1jy = Jbv.y;

        float dcx = Jav.x - Ia.x;
        float dcy = Jav.y - Ia.y;

        float M00 = fmaf(a0ix, a0jx, a0iy * a0jy);
        float M01 = fmaf(a0ix, a1jx, a0iy * a1jy);
        float M10 = fmaf(a1ix, a0jx, a1iy * a0jy);
        float M11 = fmaf(a1ix, a1jx, a1iy * a1jy);

        float dA0 = fmaf(dcx, a0ix, dcy * a0iy);
        float dA1 = fmaf(dcx, a1ix, dcy * a1iy);
        float dB0 = fmaf(dcx, a0jx, dcy * a0jy);
        float dB1 = fmaf(dcx, a1jx, dcy * a1jy);

        float LbA0 = fabsf(M00) + fabsf(M01);
        float LbA1 = fabsf(M10) + fabsf(M11);
        float LbB0 = fabsf(M00) + fabsf(M10);
        float LbB1 = fabsf(M01) + fabsf(M11);

        float S0 = Ib.z  + LbA0;
        float S1 = Ib.w  + LbA1;
        float S2 = Jbv.z + LbB0;
        float S3 = Jbv.w + LbB1;

        float t0 = fmaf(0.5f, S0, -fabsf(dA0));
        float t1 = fmaf(0.5f, S1, -fabsf(dA1));
        float t2 = fmaf(0.5f, S2, -fabsf(dB0));
        float t3 = fmaf(0.5f, S3, -fabsf(dB1));
        float m = fminf(fminf(t0, t1), fminf(t2, t3));

        float g0 = giou_eval(Ib.z,  LbA0, S0, t0, dA0);
        float g1 = giou_eval(Ib.w,  LbA1, S1, t1, dA1);
        float g2 = giou_eval(Jbv.z, LbB0, S2, t2, dB0);
        float g3 = giou_eval(Jbv.w, LbB1, S3, t3, dB1);

        float gmin = fminf(fminf(g0, g1), fminf(g2, g3));
        float res = (m > 0.0f) ? fmaxf(gmin, 0.0f) : 0.0f;

        const int gi = ti + iloc;
        const int gj = tj + jloc;
        out[(size_t)gi * NB + gj] = res;
        out[(size_t)gj * NB + gi] = res;   // mirror (value-identical on overlap)
    }
}

extern "C" void kernel_launch(void* const* d_in, const int* in_sizes, int n_in,
                              void* d_out, int out_size) {
    const float* boxes = (const float*)d_in[0];
    float* out = (float*)d_out;
    (void)in_sizes; (void)n_in; (void)out_size;

    pair_kernel<<<4160, 256>>>(boxes, out);
}